// round 1
// baseline (speedup 1.0000x reference)
#include <cuda_runtime.h>
#include <cuda_bf16.h>

#define N_DIM 512
#define N_TRIPLES 200000

__global__ __launch_bounds__(256) void classifier_head_kernel(
    const float* __restrict__ emb,     // [N_NODES, 512]
    const float* __restrict__ W,       // [64, 1024]
    const float* __restrict__ b,       // [64]
    const int*   __restrict__ triples, // [3, N_TRIPLES]
    float*       __restrict__ out,     // [N_TRIPLES]
    int n)
{
    int warp = (int)((blockIdx.x * blockDim.x + threadIdx.x) >> 5);
    int lane = threadIdx.x & 31;
    if (warp >= n) return;

    int s_idx = triples[warp];
    int r_idx = triples[n + warp];
    int o_idx = triples[2 * n + warp];

    const float4* sp  = (const float4*)(emb + (size_t)s_idx * N_DIM);
    const float4* op  = (const float4*)(emb + (size_t)o_idx * N_DIM);
    const float4* wsp = (const float4*)(W + (size_t)r_idx * (2 * N_DIM));
    const float4* wop = wsp + (N_DIM / 4);  // second half of W row

    float acc = 0.0f;
    // 512 floats = 128 float4 per row; 32 lanes -> 4 float4 per lane per row.
    #pragma unroll
    for (int i = 0; i < 4; i++) {
        int j = lane + 32 * i;
        float4 sv = sp[j];
        float4 wv = wsp[j];
        float4 ov = op[j];
        float4 uv = wop[j];
        acc = fmaf(sv.x, wv.x, acc);
        acc = fmaf(sv.y, wv.y, acc);
        acc = fmaf(sv.z, wv.z, acc);
        acc = fmaf(sv.w, wv.w, acc);
        acc = fmaf(ov.x, uv.x, acc);
        acc = fmaf(ov.y, uv.y, acc);
        acc = fmaf(ov.z, uv.z, acc);
        acc = fmaf(ov.w, uv.w, acc);
    }

    // Warp tree reduction
    #pragma unroll
    for (int off = 16; off > 0; off >>= 1)
        acc += __shfl_xor_sync(0xFFFFFFFFu, acc, off);

    if (lane == 0)
        out[warp] = acc + __ldg(&b[r_idx]);
}

extern "C" void kernel_launch(void* const* d_in, const int* in_sizes, int n_in,
                              void* d_out, int out_size)
{
    const float* emb     = (const float*)d_in[0];
    const float* W       = (const float*)d_in[1];
    const float* b       = (const float*)d_in[2];
    const int*   triples = (const int*)d_in[3];
    float*       out     = (float*)d_out;

    int n = out_size;  // N_TRIPLES
    // one warp per triple, 8 warps per block
    int blocks = (n + 7) / 8;
    classifier_head_kernel<<<blocks, 256>>>(emb, W, b, triples, out, n);
}